// round 6
// baseline (speedup 1.0000x reference)
#include <cuda_runtime.h>

#define EPS 1e-5f
typedef unsigned long long ull;

// ---------------- packed f32x2 helpers (B300 dual-rate FP32 path) ----------
__device__ __forceinline__ ull pack2(float x, float y) {
    ull r; asm("mov.b64 %0, {%1,%2};" : "=l"(r) : "f"(x), "f"(y)); return r;
}
__device__ __forceinline__ ull dup2(float x) { return pack2(x, x); }
__device__ __forceinline__ void unpack2(ull a, float& x, float& y) {
    asm("mov.b64 {%0,%1}, %2;" : "=f"(x), "=f"(y) : "l"(a));
}
__device__ __forceinline__ ull ffma2(ull a, ull b, ull c) {
    ull d; asm("fma.rn.f32x2 %0, %1, %2, %3;" : "=l"(d) : "l"(a), "l"(b), "l"(c));
    return d;
}
__device__ __forceinline__ ull relu2(ull a) {
    float x, y; unpack2(a, x, y);
    x = fmaxf(x, 0.f); y = fmaxf(y, 0.f);
    return pack2(x, y);
}
__device__ __forceinline__ float warp_sum(float v) {
#pragma unroll
    for (int o = 16; o > 0; o >>= 1)
        v += __shfl_down_sync(0xffffffffu, v, o);
    return v;
}

// ---------------- scratch (device globals: no allocs allowed) --------------
__device__ float g_pooled[2 * 768];
__device__ float g_G1[2 * 153];     // ctrl_w[:, :256] @ x_feat + ctrl_b
__device__ float g_G2[32 * 153];    // ctrl_w[:, 256:] @ te
__device__ float g_part[2 * 16 * 24 * 2];
__device__ float g_stats[2 * 16 * 2];   // (mean, rstd) per (b, group)

// ============================================================================
// Kernel 1: k_stats — fused independent stats passes
//   blocks   0..767: GN2 partial sums over out (2,48,64^3)
//   blocks 768..799: GN1(x)+ReLU+pool -> g_pooled (2,768)
// ============================================================================
__global__ void k_stats(const float* __restrict__ outp,
                        const float* __restrict__ x,
                        const float* __restrict__ g1g,
                        const float* __restrict__ g1b) {
    __shared__ float rs[256], rss[256];
    int t = threadIdx.x;

    if (blockIdx.x < 768) {
        // ---- GN2 partial sums ----
        int bg = blockIdx.x / 24, part = blockIdx.x % 24;
        const float4* base = (const float4*)(outp + (size_t)bg * 786432) + (size_t)part * 8192;
        float s = 0.f, ss = 0.f;
        for (int i = t; i < 8192; i += 256) {
            float4 v = base[i];
            s  += v.x + v.y + v.z + v.w;
            ss += v.x * v.x + v.y * v.y + v.z * v.z + v.w * v.w;
        }
        rs[t] = s; rss[t] = ss;
        __syncthreads();
        for (int o = 128; o > 0; o >>= 1) {
            if (t < o) { rs[t] += rs[t + o]; rss[t] += rss[t + o]; }
            __syncthreads();
        }
        if (t == 0) {
            g_part[blockIdx.x * 2]     = rs[0];
            g_part[blockIdx.x * 2 + 1] = rss[0];
        }
    } else {
        // ---- GN1 + ReLU + pool ----
        int bg = blockIdx.x - 768;            // 0..31
        int b = bg >> 4, g = bg & 15;
        const float* base = x + ((size_t)b * 768 + (size_t)g * 48) * 512;

        float s = 0.f, ss = 0.f;
        const float4* b4 = (const float4*)base;
        for (int i = t; i < 6144; i += 256) {
            float4 v = b4[i];
            s  += v.x + v.y + v.z + v.w;
            ss += v.x * v.x + v.y * v.y + v.z * v.z + v.w * v.w;
        }
        rs[t] = s; rss[t] = ss;
        __syncthreads();
        for (int o = 128; o > 0; o >>= 1) {
            if (t < o) { rs[t] += rs[t + o]; rss[t] += rss[t + o]; }
            __syncthreads();
        }
        __shared__ float s_mean, s_rstd;
        if (t == 0) {
            float mean = rs[0] * (1.f / 24576.f);
            float var  = rss[0] * (1.f / 24576.f) - mean * mean;
            s_mean = mean;
            s_rstd = rsqrtf(var + EPS);
        }
        __syncthreads();
        float mean = s_mean, rstd = s_rstd;

        int warp = t >> 5, lane = t & 31;
        for (int c = warp; c < 48; c += 8) {
            int ch = g * 48 + c;
            float sc = rstd * g1g[ch];
            float sh = g1b[ch] - mean * sc;
            const float* cb = base + (size_t)c * 512;
            float acc = 0.f;
            for (int i = lane; i < 512; i += 32)
                acc += fmaxf(fmaf(cb[i], sc, sh), 0.f);
            acc = warp_sum(acc);
            if (lane == 0) g_pooled[b * 768 + ch] = acc * (1.f / 512.f);
        }
    }
}

// ============================================================================
// Kernel 2: k_ctrl — controller path + GN2 finalize
//   blocks 0,1  : xfeat[b] (in smem) then G1[b,:]
//   blocks 2..33: G2[cls,:]
//   block  34   : gn2 finalize -> g_stats
// ============================================================================
__global__ void k_ctrl(const float* __restrict__ gap_w,
                       const float* __restrict__ gap_b,
                       const float* __restrict__ ctrl_w,
                       const float* __restrict__ ctrl_b,
                       const float* __restrict__ te) {
    int blk = blockIdx.x;
    int t = threadIdx.x;
    int warp = t >> 5, lane = t & 31;

    if (blk == 34) {
        if (t < 32) {
            int bg = t;
            float s = 0.f, ss = 0.f;
            for (int p = 0; p < 24; p++) {
                s  += g_part[(bg * 24 + p) * 2];
                ss += g_part[(bg * 24 + p) * 2 + 1];
            }
            float mean = s * (1.f / 786432.f);
            float var  = ss * (1.f / 786432.f) - mean * mean;
            g_stats[bg * 2]     = mean;
            g_stats[bg * 2 + 1] = rsqrtf(var + EPS);
        }
        return;
    }

    __shared__ float sv[256];

    if (blk < 2) {
        // ---- xfeat for batch b, kept in smem ----
        int b = blk;
        __shared__ float sp[768];
        for (int i = t; i < 768; i += 256) sp[i] = g_pooled[b * 768 + i];
        __syncthreads();

        for (int r = 0; r < 32; r += 4) {
            int f = warp * 32 + r;
            const float* w0 = gap_w + (size_t)(f + 0) * 768;
            const float* w1 = gap_w + (size_t)(f + 1) * 768;
            const float* w2 = gap_w + (size_t)(f + 2) * 768;
            const float* w3 = gap_w + (size_t)(f + 3) * 768;
            float a0 = 0.f, a1 = 0.f, a2 = 0.f, a3 = 0.f;
#pragma unroll 4
            for (int it = 0; it < 24; it++) {
                int i = it * 32 + lane;
                float p = sp[i];
                a0 = fmaf(w0[i], p, a0);
                a1 = fmaf(w1[i], p, a1);
                a2 = fmaf(w2[i], p, a2);
                a3 = fmaf(w3[i], p, a3);
            }
            a0 = warp_sum(a0); a1 = warp_sum(a1);
            a2 = warp_sum(a2); a3 = warp_sum(a3);
            if (lane == 0) {
                sv[f + 0] = a0 + gap_b[f + 0];
                sv[f + 1] = a1 + gap_b[f + 1];
                sv[f + 2] = a2 + gap_b[f + 2];
                sv[f + 3] = a3 + gap_b[f + 3];
            }
        }
        __syncthreads();

        // ---- G1[b,p] = ctrl_w[p,:256]·sv + ctrl_b[p] ----
        for (int pb = warp * 4; pb < 153; pb += 32) {
            float a[4] = {0.f, 0.f, 0.f, 0.f};
#pragma unroll
            for (int j = 0; j < 4; j++) {
                int p = pb + j;
                if (p < 153) {
                    const float* wr = ctrl_w + (size_t)p * 512;
#pragma unroll
                    for (int it = 0; it < 8; it++)
                        a[j] = fmaf(wr[it * 32 + lane], sv[it * 32 + lane], a[j]);
                }
            }
#pragma unroll
            for (int j = 0; j < 4; j++) {
                a[j] = warp_sum(a[j]);
                if (lane == 0 && pb + j < 153)
                    g_G1[b * 153 + pb + j] = a[j] + ctrl_b[pb + j];
            }
        }
    } else {
        // ---- G2[cls,p] = ctrl_w[p,256:]·te[cls] ----
        int cls = blk - 2;
        sv[t] = te[cls * 256 + t];
        __syncthreads();

        for (int pb = warp * 4; pb < 153; pb += 32) {
            float a[4] = {0.f, 0.f, 0.f, 0.f};
#pragma unroll
            for (int j = 0; j < 4; j++) {
                int p = pb + j;
                if (p < 153) {
                    const float* wr = ctrl_w + (size_t)p * 512 + 256;
#pragma unroll
                    for (int it = 0; it < 8; it++)
                        a[j] = fmaf(wr[it * 32 + lane], sv[it * 32 + lane], a[j]);
                }
            }
#pragma unroll
            for (int j = 0; j < 4; j++) {
                a[j] = warp_sum(a[j]);
                if (lane == 0 && pb + j < 153)
                    g_G2[cls * 153 + pb + j] = a[j];
            }
        }
    }
}

// ============================================================================
// Kernel 3: fused GN2+ReLU -> h0 (48->8) -> 32x per-class MLP 8->8->8->1
// EXACT round-4 body (depth-1 prefetch): known-good, no spills.
// ============================================================================
__global__ void __launch_bounds__(256, 2)
k_main(const float* __restrict__ outp,
       const float* __restrict__ g2g, const float* __restrict__ g2b,
       const float* __restrict__ pre_w, const float* __restrict__ pre_b,
       float* __restrict__ dst) {
    __shared__ ull s_params[32 * 154];         // pad 154 -> 16B align
    __shared__ ull s_prew[48 * 8];             // transposed [c][o]
    __shared__ ull s_preb[8];
    __shared__ ulonglong2 s_gn[48];            // .x=scale .y=shift (dup2'd)

    int b = blockIdx.x >> 8;          // 256 chunks per batch
    int chunk = blockIdx.x & 255;
    int t = threadIdx.x;

    for (int i = t; i < 32 * 154; i += 256) {
        int cls = i / 154, p = i - cls * 154;
        if (p < 153)
            s_params[i] = dup2(g_G1[b * 153 + p] + g_G2[cls * 153 + p]);
    }
    for (int i = t; i < 384; i += 256) {
        int c = i >> 3, o = i & 7;
        s_prew[i] = dup2(pre_w[o * 48 + c]);
    }
    if (t < 8) s_preb[t] = dup2(pre_b[t]);
    if (t >= 32 && t < 80) {
        int c = t - 32;
        int g = c / 3;
        float mean = g_stats[(b * 16 + g) * 2];
        float rstd = g_stats[(b * 16 + g) * 2 + 1];
        float sc = rstd * g2g[c];
        s_gn[c].x = dup2(sc);
        s_gn[c].y = dup2(g2b[c] - mean * sc);
    }
    __syncthreads();

    int u0 = chunk * 512 + t;
    const ull* src = (const ull*)outp + (size_t)b * 48 * 131072 + u0;

    ull h0[8][2];
#pragma unroll
    for (int o = 0; o < 8; o++) {
        h0[o][0] = s_preb[o];
        h0[o][1] = s_preb[o];
    }

    // GN2 + ReLU + h0 = pre_w·g, next-channel prefetch, paired weight loads
    ull n0 = src[0], n1 = src[256];
    for (int c = 0; c < 48; c++) {
        ull v0 = n0, v1 = n1;
        if (c < 47) {
            const ull* nx = src + (size_t)(c + 1) * 131072;
            n0 = nx[0]; n1 = nx[256];
        }
        ulonglong2 gn = s_gn[c];
        ull g0 = relu2(ffma2(v0, gn.x, gn.y));
        ull g1 = relu2(ffma2(v1, gn.x, gn.y));
        const ulonglong2* W = (const ulonglong2*)(s_prew + c * 8);
#pragma unroll
        for (int oo = 0; oo < 4; oo++) {
            ulonglong2 w2 = W[oo];
            h0[2 * oo][0]     = ffma2(w2.x, g0, h0[2 * oo][0]);
            h0[2 * oo][1]     = ffma2(w2.x, g1, h0[2 * oo][1]);
            h0[2 * oo + 1][0] = ffma2(w2.y, g0, h0[2 * oo + 1][0]);
            h0[2 * oo + 1][1] = ffma2(w2.y, g1, h0[2 * oo + 1][1]);
        }
    }

    ull* dbase = (ull*)dst + (size_t)b * 32 * 131072 + u0;

    for (int cls = 0; cls < 32; cls++) {
        const ull* P = s_params + cls * 154;
        const ulonglong2* P2 = (const ulonglong2*)P;

        // ---- layer 1: t1 = relu(W1 h0 + b1) ----
        ull t1[8][2];
#pragma unroll
        for (int j = 0; j < 8; j++) {
            ull bias = P[136 + j];
            t1[j][0] = bias;
            t1[j][1] = bias;
        }
#pragma unroll
        for (int kk = 0; kk < 4; kk++) {
#pragma unroll
            for (int j = 0; j < 8; j++) {
                ulonglong2 w2 = P2[j * 4 + kk];
                t1[j][0] = ffma2(w2.x, h0[2 * kk][0],     t1[j][0]);
                t1[j][1] = ffma2(w2.x, h0[2 * kk][1],     t1[j][1]);
                t1[j][0] = ffma2(w2.y, h0[2 * kk + 1][0], t1[j][0]);
                t1[j][1] = ffma2(w2.y, h0[2 * kk + 1][1], t1[j][1]);
            }
        }
#pragma unroll
        for (int j = 0; j < 8; j++) {
            t1[j][0] = relu2(t1[j][0]);
            t1[j][1] = relu2(t1[j][1]);
        }

        // ---- layers 2+3 folded ----
        ull y0 = P[152], y1 = P[152];
#pragma unroll
        for (int j = 0; j < 8; j++) {
            ull bias = P[144 + j];
            ull t20 = bias, t21 = bias;
#pragma unroll
            for (int kk = 0; kk < 4; kk++) {
                ulonglong2 w2 = P2[32 + j * 4 + kk];
                t20 = ffma2(w2.x, t1[2 * kk][0],     t20);
                t21 = ffma2(w2.x, t1[2 * kk][1],     t21);
                t20 = ffma2(w2.y, t1[2 * kk + 1][0], t20);
                t21 = ffma2(w2.y, t1[2 * kk + 1][1], t21);
            }
            ull w3 = P[128 + j];
            y0 = ffma2(w3, relu2(t20), y0);
            y1 = ffma2(w3, relu2(t21), y1);
        }

        ull* dp = dbase + (size_t)cls * 131072;
        dp[0]   = y0;
        dp[256] = y1;
    }
}

// ============================================================================
extern "C" void kernel_launch(void* const* d_in, const int* in_sizes, int n_in,
                              void* d_out, int out_size) {
    const float* x      = (const float*)d_in[0];
    const float* outp   = (const float*)d_in[1];
    const float* te     = (const float*)d_in[2];
    const float* gn1_g  = (const float*)d_in[3];
    const float* gn1_b  = (const float*)d_in[4];
    const float* gap_w  = (const float*)d_in[5];
    const float* gap_b  = (const float*)d_in[6];
    const float* ctrl_w = (const float*)d_in[7];
    const float* ctrl_b = (const float*)d_in[8];
    const float* gn2_g  = (const float*)d_in[9];
    const float* gn2_b  = (const float*)d_in[10];
    const float* pre_w  = (const float*)d_in[11];
    const float* pre_b  = (const float*)d_in[12];
    float* dst = (float*)d_out;

    k_stats<<<800, 256>>>(outp, x, gn1_g, gn1_b);
    k_ctrl<<<35, 256>>>(gap_w, gap_b, ctrl_w, ctrl_b, te);
    k_main<<<512, 256>>>(outp, gn2_g, gn2_b, pre_w, pre_b, dst);
}

// round 7
// speedup vs baseline: 1.3670x; 1.3670x over previous
#include <cuda_runtime.h>

#define EPS 1e-5f
typedef unsigned long long ull;

// ---------------- packed f32x2 helpers (B300 dual-rate FP32 path) ----------
__device__ __forceinline__ ull pack2(float x, float y) {
    ull r; asm("mov.b64 %0, {%1,%2};" : "=l"(r) : "f"(x), "f"(y)); return r;
}
__device__ __forceinline__ ull dup2(float x) { return pack2(x, x); }
__device__ __forceinline__ void unpack2(ull a, float& x, float& y) {
    asm("mov.b64 {%0,%1}, %2;" : "=f"(x), "=f"(y) : "l"(a));
}
__device__ __forceinline__ ull ffma2(ull a, ull b, ull c) {
    ull d; asm("fma.rn.f32x2 %0, %1, %2, %3;" : "=l"(d) : "l"(a), "l"(b), "l"(c));
    return d;
}
__device__ __forceinline__ ull relu2(ull a) {
    float x, y; unpack2(a, x, y);
    x = fmaxf(x, 0.f); y = fmaxf(y, 0.f);
    return pack2(x, y);
}
__device__ __forceinline__ float warp_sum(float v) {
#pragma unroll
    for (int o = 16; o > 0; o >>= 1)
        v += __shfl_down_sync(0xffffffffu, v, o);
    return v;
}

// ---------------- scratch (device globals: no allocs allowed) --------------
__device__ float g_pooled[2 * 768];
__device__ float g_xfeat[2 * 256];
__device__ float g_G1[2 * 153];     // ctrl_w[:, :256] @ x_feat + ctrl_b
__device__ float g_G2[32 * 153];    // ctrl_w[:, 256:] @ te
__device__ float g_part[2 * 16 * 24 * 2];
__device__ float g_stats[2 * 16 * 2];   // (mean, rstd) per (b, group)

// ============================================================================
// Kernel A: GN1(x) + ReLU + spatial mean -> pooled (2,768)   [round-4 exact]
// ============================================================================
__global__ void k_gn1_pool(const float* __restrict__ x,
                           const float* __restrict__ g1g,
                           const float* __restrict__ g1b) {
    int bg = blockIdx.x;            // 0..31
    int b = bg >> 4, g = bg & 15;
    const float* base = x + ((size_t)b * 768 + (size_t)g * 48) * 512;

    float s = 0.f, ss = 0.f;
    const float4* b4 = (const float4*)base;
    for (int i = threadIdx.x; i < 6144; i += 256) {
        float4 v = b4[i];
        s  += v.x + v.y + v.z + v.w;
        ss += v.x * v.x + v.y * v.y + v.z * v.z + v.w * v.w;
    }
    __shared__ float rs[256], rss[256];
    rs[threadIdx.x] = s; rss[threadIdx.x] = ss;
    __syncthreads();
    for (int o = 128; o > 0; o >>= 1) {
        if (threadIdx.x < o) {
            rs[threadIdx.x]  += rs[threadIdx.x + o];
            rss[threadIdx.x] += rss[threadIdx.x + o];
        }
        __syncthreads();
    }
    __shared__ float s_mean, s_rstd;
    if (threadIdx.x == 0) {
        float mean = rs[0] * (1.f / 24576.f);
        float var  = rss[0] * (1.f / 24576.f) - mean * mean;
        s_mean = mean;
        s_rstd = rsqrtf(var + EPS);
    }
    __syncthreads();
    float mean = s_mean, rstd = s_rstd;

    int warp = threadIdx.x >> 5, lane = threadIdx.x & 31;
    for (int c = warp; c < 48; c += 8) {
        int ch = g * 48 + c;
        float sc = rstd * g1g[ch];
        float sh = g1b[ch] - mean * sc;
        const float* cb = base + (size_t)c * 512;
        float acc = 0.f;
        for (int i = lane; i < 512; i += 32)
            acc += fmaxf(fmaf(cb[i], sc, sh), 0.f);
        acc = warp_sum(acc);
        if (lane == 0) g_pooled[b * 768 + ch] = acc * (1.f / 512.f);
    }
}

// ============================================================================
// Kernel B1: x_feat = pooled @ gap_w.T + gap_b   (2,256)     [round-4 exact]
// ============================================================================
__global__ void k_xfeat(const float* __restrict__ gap_w,
                        const float* __restrict__ gap_b) {
    int b   = blockIdx.x >> 3;        // 16 blocks: 8 per batch
    int sub = blockIdx.x & 7;
    int warp = threadIdx.x >> 5, lane = threadIdx.x & 31;

    __shared__ float sp[768];
    for (int i = threadIdx.x; i < 768; i += 256) sp[i] = g_pooled[b * 768 + i];
    __syncthreads();

    for (int q = 0; q < 4; q++) {
        int f = sub * 32 + q * 8 + warp;
        const float* wr = gap_w + (size_t)f * 768;
        float acc = 0.f;
        for (int i = lane; i < 768; i += 32)
            acc = fmaf(wr[i], sp[i], acc);
        acc = warp_sum(acc);
        if (lane == 0) g_xfeat[b * 256 + f] = acc + gap_b[f];
    }
}

// ============================================================================
// Kernel B2: G1/G2 — 4-row interleaved dots (ONLY change vs round 4)
//   blocks 0,1  : G1[b,p]  = ctrl_w[p,:256]·x_feat[b] + ctrl_b[p]
//   blocks 2..33: G2[cls,p] = ctrl_w[p,256:]·te[cls]
// ============================================================================
__global__ void k_gparams(const float* __restrict__ ctrl_w,
                          const float* __restrict__ ctrl_b,
                          const float* __restrict__ te) {
    int blk = blockIdx.x;             // 0..33
    int t = threadIdx.x;
    int warp = t >> 5, lane = t & 31;

    __shared__ float sv[256];
    const float* wbase;
    float* dst;
    bool addb;
    if (blk < 2) {
        sv[t] = g_xfeat[blk * 256 + t];
        wbase = ctrl_w;
        dst = g_G1 + blk * 153;
        addb = true;
    } else {
        int c = blk - 2;
        sv[t] = te[c * 256 + t];
        wbase = ctrl_w + 256;
        dst = g_G2 + c * 153;
        addb = false;
    }
    __syncthreads();

    // warp handles 4 consecutive rows at a time -> 4 latency chains in flight
    for (int pb = warp * 4; pb < 153; pb += 32) {
        float a[4] = {0.f, 0.f, 0.f, 0.f};
#pragma unroll
        for (int j = 0; j < 4; j++) {
            int p = pb + j;
            if (p < 153) {
                const float* wr = wbase + (size_t)p * 512;
#pragma unroll
                for (int it = 0; it < 8; it++)
                    a[j] = fmaf(wr[it * 32 + lane], sv[it * 32 + lane], a[j]);
            }
        }
#pragma unroll
        for (int j = 0; j < 4; j++) {
            a[j] = warp_sum(a[j]);
            if (lane == 0 && pb + j < 153)
                dst[pb + j] = addb ? (a[j] + ctrl_b[pb + j]) : a[j];
        }
    }
}

// ============================================================================
// Kernel C: GN2 partial sums over out (2,48,64^3)            [round-4 exact]
// ============================================================================
__global__ void k_gn2_part(const float* __restrict__ outp) {
    int bg = blockIdx.x / 24, part = blockIdx.x % 24;
    const float4* base = (const float4*)(outp + (size_t)bg * 786432) + (size_t)part * 8192;
    float s = 0.f, ss = 0.f;
    for (int i = threadIdx.x; i < 8192; i += 256) {
        float4 v = base[i];
        s  += v.x + v.y + v.z + v.w;
        ss += v.x * v.x + v.y * v.y + v.z * v.z + v.w * v.w;
    }
    __shared__ float rs[256], rss[256];
    rs[threadIdx.x] = s; rss[threadIdx.x] = ss;
    __syncthreads();
    for (int o = 128; o > 0; o >>= 1) {
        if (threadIdx.x < o) {
            rs[threadIdx.x]  += rs[threadIdx.x + o];
            rss[threadIdx.x] += rss[threadIdx.x + o];
        }
        __syncthreads();
    }
    if (threadIdx.x == 0) {
        g_part[blockIdx.x * 2]     = rs[0];
        g_part[blockIdx.x * 2 + 1] = rss[0];
    }
}

__global__ void k_gn2_fin() {
    int bg = threadIdx.x;   // 32 threads
    float s = 0.f, ss = 0.f;
    for (int p = 0; p < 24; p++) {
        s  += g_part[(bg * 24 + p) * 2];
        ss += g_part[(bg * 24 + p) * 2 + 1];
    }
    float mean = s * (1.f / 786432.f);
    float var  = ss * (1.f / 786432.f) - mean * mean;
    g_stats[bg * 2]     = mean;
    g_stats[bg * 2 + 1] = rsqrtf(var + EPS);
}

// ============================================================================
// Kernel E: fused GN2+ReLU -> h0 -> 32x per-class MLP        [round-4 exact]
// ============================================================================
__global__ void __launch_bounds__(256, 2)
k_main(const float* __restrict__ outp,
       const float* __restrict__ g2g, const float* __restrict__ g2b,
       const float* __restrict__ pre_w, const float* __restrict__ pre_b,
       float* __restrict__ dst) {
    __shared__ ull s_params[32 * 154];         // pad 154 -> 16B align
    __shared__ ull s_prew[48 * 8];             // transposed [c][o]
    __shared__ ull s_preb[8];
    __shared__ ulonglong2 s_gn[48];            // .x=scale .y=shift (dup2'd)

    int b = blockIdx.x >> 8;          // 256 chunks per batch
    int chunk = blockIdx.x & 255;
    int t = threadIdx.x;

    for (int i = t; i < 32 * 154; i += 256) {
        int cls = i / 154, p = i - cls * 154;
        if (p < 153)
            s_params[i] = dup2(g_G1[b * 153 + p] + g_G2[cls * 153 + p]);
    }
    for (int i = t; i < 384; i += 256) {
        int c = i >> 3, o = i & 7;
        s_prew[i] = dup2(pre_w[o * 48 + c]);
    }
    if (t < 8) s_preb[t] = dup2(pre_b[t]);
    if (t >= 32 && t < 80) {
        int c = t - 32;
        int g = c / 3;
        float mean = g_stats[(b * 16 + g) * 2];
        float rstd = g_stats[(b * 16 + g) * 2 + 1];
        float sc = rstd * g2g[c];
        s_gn[c].x = dup2(sc);
        s_gn[c].y = dup2(g2b[c] - mean * sc);
    }
    __syncthreads();

    int u0 = chunk * 512 + t;
    const ull* src = (const ull*)outp + (size_t)b * 48 * 131072 + u0;

    ull h0[8][2];
#pragma unroll
    for (int o = 0; o < 8; o++) {
        h0[o][0] = s_preb[o];
        h0[o][1] = s_preb[o];
    }

    ull n0 = src[0], n1 = src[256];
    for (int c = 0; c < 48; c++) {
        ull v0 = n0, v1 = n1;
        if (c < 47) {
            const ull* nx = src + (size_t)(c + 1) * 131072;
            n0 = nx[0]; n1 = nx[256];
        }
        ulonglong2 gn = s_gn[c];
        ull g0 = relu2(ffma2(v0, gn.x, gn.y));
        ull g1 = relu2(ffma2(v1, gn.x, gn.y));
        const ulonglong2* W = (const ulonglong2*)(s_prew + c * 8);
#pragma unroll
        for (int oo = 0; oo < 4; oo++) {
            ulonglong2 w2 = W[oo];
            h0[2 * oo][0]     = ffma2(w2.x, g0, h0[2 * oo][0]);
            h0[2 * oo][1]     = ffma2(w2.x, g1, h0[2 * oo][1]);
            h0[2 * oo + 1][0] = ffma2(w2.y, g0, h0[2 * oo + 1][0]);
            h0[2 * oo + 1][1] = ffma2(w2.y, g1, h0[2 * oo + 1][1]);
        }
    }

    ull* dbase = (ull*)dst + (size_t)b * 32 * 131072 + u0;

    for (int cls = 0; cls < 32; cls++) {
        const ull* P = s_params + cls * 154;
        const ulonglong2* P2 = (const ulonglong2*)P;

        ull t1[8][2];
#pragma unroll
        for (int j = 0; j < 8; j++) {
            ull bias = P[136 + j];
            t1[j][0] = bias;
            t1[j][1] = bias;
        }
#pragma unroll
        for (int kk = 0; kk < 4; kk++) {
#pragma unroll
            for (int j = 0; j < 8; j++) {
                ulonglong2 w2 = P2[j * 4 + kk];
                t1[j][0] = ffma2(w2.x, h0[2 * kk][0],     t1[j][0]);
                t1[j][1] = ffma2(w2.x, h0[2 * kk][1],     t1[j][1]);
                t1[j][0] = ffma2(w2.y, h0[2 * kk + 1][0], t1[j][0]);
                t1[j][1] = ffma2(w2.y, h0[2 * kk + 1][1], t1[j][1]);
            }
        }
#pragma unroll
        for (int j = 0; j < 8; j++) {
            t1[j][0] = relu2(t1[j][0]);
            t1[j][1] = relu2(t1[j][1]);
        }

        ull y0 = P[152], y1 = P[152];
#pragma unroll
        for (int j = 0; j < 8; j++) {
            ull bias = P[144 + j];
            ull t20 = bias, t21 = bias;
#pragma unroll
            for (int kk = 0; kk < 4; kk++) {
                ulonglong2 w2 = P2[32 + j * 4 + kk];
                t20 = ffma2(w2.x, t1[2 * kk][0],     t20);
                t21 = ffma2(w2.x, t1[2 * kk][1],     t21);
                t20 = ffma2(w2.y, t1[2 * kk + 1][0], t20);
                t21 = ffma2(w2.y, t1[2 * kk + 1][1], t21);
            }
            ull w3 = P[128 + j];
            y0 = ffma2(w3, relu2(t20), y0);
            y1 = ffma2(w3, relu2(t21), y1);
        }

        ull* dp = dbase + (size_t)cls * 131072;
        dp[0]   = y0;
        dp[256] = y1;
    }
}

// ============================================================================
extern "C" void kernel_launch(void* const* d_in, const int* in_sizes, int n_in,
                              void* d_out, int out_size) {
    const float* x      = (const float*)d_in[0];
    const float* outp   = (const float*)d_in[1];
    const float* te     = (const float*)d_in[2];
    const float* gn1_g  = (const float*)d_in[3];
    const float* gn1_b  = (const float*)d_in[4];
    const float* gap_w  = (const float*)d_in[5];
    const float* gap_b  = (const float*)d_in[6];
    const float* ctrl_w = (const float*)d_in[7];
    const float* ctrl_b = (const float*)d_in[8];
    const float* gn2_g  = (const float*)d_in[9];
    const float* gn2_b  = (const float*)d_in[10];
    const float* pre_w  = (const float*)d_in[11];
    const float* pre_b  = (const float*)d_in[12];
    float* dst = (float*)d_out;

    // round-4 launch sequence (known 188.9us), only k_gparams body improved
    k_gn2_part<<<768, 256>>>(outp);
    k_gn1_pool<<<32, 256>>>(x, gn1_g, gn1_b);
    k_xfeat<<<16, 256>>>(gap_w, gap_b);
    k_gparams<<<34, 256>>>(ctrl_w, ctrl_b, te);
    k_gn2_fin<<<1, 32>>>();
    k_main<<<512, 256>>>(outp, gn2_g, gn2_b, pre_w, pre_b, dst);
}

// round 8
// speedup vs baseline: 1.5916x; 1.1643x over previous
#include <cuda_runtime.h>

#define EPS 1e-5f
typedef unsigned long long ull;

// ---------------- packed f32x2 helpers (B300 dual-rate FP32 path) ----------
__device__ __forceinline__ ull pack2(float x, float y) {
    ull r; asm("mov.b64 %0, {%1,%2};" : "=l"(r) : "f"(x), "f"(y)); return r;
}
__device__ __forceinline__ ull dup2(float x) { return pack2(x, x); }
__device__ __forceinline__ void unpack2(ull a, float& x, float& y) {
    asm("mov.b64 {%0,%1}, %2;" : "=f"(x), "=f"(y) : "l"(a));
}
__device__ __forceinline__ ull ffma2(ull a, ull b, ull c) {
    ull d; asm("fma.rn.f32x2 %0, %1, %2, %3;" : "=l"(d) : "l"(a), "l"(b), "l"(c));
    return d;
}
__device__ __forceinline__ ull relu2(ull a) {
    float x, y; unpack2(a, x, y);
    x = fmaxf(x, 0.f); y = fmaxf(y, 0.f);
    return pack2(x, y);
}
__device__ __forceinline__ float warp_sum(float v) {
#pragma unroll
    for (int o = 16; o > 0; o >>= 1)
        v += __shfl_down_sync(0xffffffffu, v, o);
    return v;
}

// ---------------- scratch (device globals: no allocs allowed) --------------
__device__ float g_pooled[2 * 768];
__device__ float g_xfeat[2 * 256];
__device__ float g_G1[2 * 153];     // ctrl_w[:, :256] @ x_feat + ctrl_b
__device__ float g_G2[32 * 153];    // ctrl_w[:, 256:] @ te
__device__ float g_part[2 * 16 * 24 * 2];
__device__ float g_stats[2 * 16 * 2];   // (mean, rstd) per (b, group)

// ============================================================================
// Kernel 1: k_stats — fused independent stats (measured-good round-5 body)
//   blocks   0..767: GN2 partial sums over out (2,48,64^3)
//   blocks 768..799: GN1(x)+ReLU+pool -> g_pooled (2,768)
// ============================================================================
__global__ void k_stats(const float* __restrict__ outp,
                        const float* __restrict__ x,
                        const float* __restrict__ g1g,
                        const float* __restrict__ g1b) {
    __shared__ float rs[256], rss[256];
    int t = threadIdx.x;

    if (blockIdx.x < 768) {
        int bg = blockIdx.x / 24, part = blockIdx.x % 24;
        const float4* base = (const float4*)(outp + (size_t)bg * 786432) + (size_t)part * 8192;
        float s = 0.f, ss = 0.f;
        for (int i = t; i < 8192; i += 256) {
            float4 v = base[i];
            s  += v.x + v.y + v.z + v.w;
            ss += v.x * v.x + v.y * v.y + v.z * v.z + v.w * v.w;
        }
        rs[t] = s; rss[t] = ss;
        __syncthreads();
        for (int o = 128; o > 0; o >>= 1) {
            if (t < o) { rs[t] += rs[t + o]; rss[t] += rss[t + o]; }
            __syncthreads();
        }
        if (t == 0) {
            g_part[blockIdx.x * 2]     = rs[0];
            g_part[blockIdx.x * 2 + 1] = rss[0];
        }
    } else {
        int bg = blockIdx.x - 768;            // 0..31
        int b = bg >> 4, g = bg & 15;
        const float* base = x + ((size_t)b * 768 + (size_t)g * 48) * 512;

        float s = 0.f, ss = 0.f;
        const float4* b4 = (const float4*)base;
        for (int i = t; i < 6144; i += 256) {
            float4 v = b4[i];
            s  += v.x + v.y + v.z + v.w;
            ss += v.x * v.x + v.y * v.y + v.z * v.z + v.w * v.w;
        }
        rs[t] = s; rss[t] = ss;
        __syncthreads();
        for (int o = 128; o > 0; o >>= 1) {
            if (t < o) { rs[t] += rs[t + o]; rss[t] += rss[t + o]; }
            __syncthreads();
        }
        __shared__ float s_mean, s_rstd;
        if (t == 0) {
            float mean = rs[0] * (1.f / 24576.f);
            float var  = rss[0] * (1.f / 24576.f) - mean * mean;
            s_mean = mean;
            s_rstd = rsqrtf(var + EPS);
        }
        __syncthreads();
        float mean = s_mean, rstd = s_rstd;

        int warp = t >> 5, lane = t & 31;
        for (int c = warp; c < 48; c += 8) {
            int ch = g * 48 + c;
            float sc = rstd * g1g[ch];
            float sh = g1b[ch] - mean * sc;
            const float* cb = base + (size_t)c * 512;
            float acc = 0.f;
            for (int i = lane; i < 512; i += 32)
                acc += fmaxf(fmaf(cb[i], sc, sh), 0.f);
            acc = warp_sum(acc);
            if (lane == 0) g_pooled[b * 768 + ch] = acc * (1.f / 512.f);
        }
    }
}

// ============================================================================
// Kernel 2: x_feat = pooled @ gap_w.T + gap_b   (2,256)     [round-7 exact]
// ============================================================================
__global__ void k_xfeat(const float* __restrict__ gap_w,
                        const float* __restrict__ gap_b) {
    int b   = blockIdx.x >> 3;
    int sub = blockIdx.x & 7;
    int warp = threadIdx.x >> 5, lane = threadIdx.x & 31;

    __shared__ float sp[768];
    for (int i = threadIdx.x; i < 768; i += 256) sp[i] = g_pooled[b * 768 + i];
    __syncthreads();

    for (int q = 0; q < 4; q++) {
        int f = sub * 32 + q * 8 + warp;
        const float* wr = gap_w + (size_t)f * 768;
        float acc = 0.f;
        for (int i = lane; i < 768; i += 32)
            acc = fmaf(wr[i], sp[i], acc);
        acc = warp_sum(acc);
        if (lane == 0) g_xfeat[b * 256 + f] = acc + gap_b[f];
    }
}

// ============================================================================
// Kernel 3: k_gparams — flat warp-per-row, 1024 threads, one latency exposure
//   blocks 0,1  : G1[b,p]  = ctrl_w[p,:256]·x_feat[b] + ctrl_b[p]
//   blocks 2..33: G2[cls,p] = ctrl_w[p,256:]·te[cls]
//   block  34   : gn2 finalize -> g_stats
// 32 warps/block; warp w handles rows w, w+32, w+64, w+96, w+128 (5 chains).
// ============================================================================
__global__ void k_gparams(const float* __restrict__ ctrl_w,
                          const float* __restrict__ ctrl_b,
                          const float* __restrict__ te) {
    int blk = blockIdx.x;
    int t = threadIdx.x;

    if (blk == 34) {
        if (t < 32) {
            int bg = t;
            float s = 0.f, ss = 0.f;
            for (int p = 0; p < 24; p++) {
                s  += g_part[(bg * 24 + p) * 2];
                ss += g_part[(bg * 24 + p) * 2 + 1];
            }
            float mean = s * (1.f / 786432.f);
            float var  = ss * (1.f / 786432.f) - mean * mean;
            g_stats[bg * 2]     = mean;
            g_stats[bg * 2 + 1] = rsqrtf(var + EPS);
        }
        return;
    }

    __shared__ float sv[256];
    const float* wbase;
    float* dst;
    bool addb = (blk < 2);
    if (addb) {
        if (t < 256) sv[t] = g_xfeat[blk * 256 + t];
        wbase = ctrl_w;
        dst = g_G1 + blk * 153;
    } else {
        int c = blk - 2;
        if (t < 256) sv[t] = te[c * 256 + t];
        wbase = ctrl_w + 256;
        dst = g_G2 + c * 153;
    }
    __syncthreads();

    int warp = t >> 5, lane = t & 31;
    int p0 = warp, p1 = warp + 32, p2 = warp + 64, p3 = warp + 96, p4 = warp + 128;
    bool v4 = (p4 < 153);
    const float* w0 = wbase + (size_t)p0 * 512;
    const float* w1 = wbase + (size_t)p1 * 512;
    const float* w2 = wbase + (size_t)p2 * 512;
    const float* w3 = wbase + (size_t)p3 * 512;
    const float* w4 = wbase + (size_t)(v4 ? p4 : 0) * 512;

    float a0 = 0.f, a1 = 0.f, a2 = 0.f, a3 = 0.f, a4 = 0.f;
#pragma unroll
    for (int it = 0; it < 8; it++) {
        int idx = it * 32 + lane;
        float v = sv[idx];
        a0 = fmaf(w0[idx], v, a0);
        a1 = fmaf(w1[idx], v, a1);
        a2 = fmaf(w2[idx], v, a2);
        a3 = fmaf(w3[idx], v, a3);
        a4 = fmaf(w4[idx], v, a4);
    }
    a0 = warp_sum(a0); a1 = warp_sum(a1); a2 = warp_sum(a2);
    a3 = warp_sum(a3); a4 = warp_sum(a4);
    if (lane == 0) {
        if (addb) {
            dst[p0] = a0 + ctrl_b[p0];
            dst[p1] = a1 + ctrl_b[p1];
            dst[p2] = a2 + ctrl_b[p2];
            dst[p3] = a3 + ctrl_b[p3];
            if (v4) dst[p4] = a4 + ctrl_b[p4];
        } else {
            dst[p0] = a0;
            dst[p1] = a1;
            dst[p2] = a2;
            dst[p3] = a3;
            if (v4) dst[p4] = a4;
        }
    }
}

// ============================================================================
// Kernel 4: fused GN2+ReLU -> h0 -> 32x per-class MLP        [round-4 exact]
// ============================================================================
__global__ void __launch_bounds__(256, 2)
k_main(const float* __restrict__ outp,
       const float* __restrict__ g2g, const float* __restrict__ g2b,
       const float* __restrict__ pre_w, const float* __restrict__ pre_b,
       float* __restrict__ dst) {
    __shared__ ull s_params[32 * 154];         // pad 154 -> 16B align
    __shared__ ull s_prew[48 * 8];             // transposed [c][o]
    __shared__ ull s_preb[8];
    __shared__ ulonglong2 s_gn[48];            // .x=scale .y=shift (dup2'd)

    int b = blockIdx.x >> 8;          // 256 chunks per batch
    int chunk = blockIdx.x & 255;
    int t = threadIdx.x;

    for (int i = t; i < 32 * 154; i += 256) {
        int cls = i / 154, p = i - cls * 154;
        if (p < 153)
            s_params[i] = dup2(g_G1[b * 153 + p] + g_G2[cls * 153 + p]);
    }
    for (int i = t; i < 384; i += 256) {
        int c = i >> 3, o = i & 7;
        s_prew[i] = dup2(pre_w[o * 48 + c]);
    }
    if (t < 8) s_preb[t] = dup2(pre_b[t]);
    if (t >= 32 && t < 80) {
        int c = t - 32;
        int g = c / 3;
        float mean = g_stats[(b * 16 + g) * 2];
        float rstd = g_stats[(b * 16 + g) * 2 + 1];
        float sc = rstd * g2g[c];
        s_gn[c].x = dup2(sc);
        s_gn[c].y = dup2(g2b[c] - mean * sc);
    }
    __syncthreads();

    int u0 = chunk * 512 + t;
    const ull* src = (const ull*)outp + (size_t)b * 48 * 131072 + u0;

    ull h0[8][2];
#pragma unroll
    for (int o = 0; o < 8; o++) {
        h0[o][0] = s_preb[o];
        h0[o][1] = s_preb[o];
    }

    ull n0 = src[0], n1 = src[256];
    for (int c = 0; c < 48; c++) {
        ull v0 = n0, v1 = n1;
        if (c < 47) {
            const ull* nx = src + (size_t)(c + 1) * 131072;
            n0 = nx[0]; n1 = nx[256];
        }
        ulonglong2 gn = s_gn[c];
        ull g0 = relu2(ffma2(v0, gn.x, gn.y));
        ull g1 = relu2(ffma2(v1, gn.x, gn.y));
        const ulonglong2* W = (const ulonglong2*)(s_prew + c * 8);
#pragma unroll
        for (int oo = 0; oo < 4; oo++) {
            ulonglong2 w2 = W[oo];
            h0[2 * oo][0]     = ffma2(w2.x, g0, h0[2 * oo][0]);
            h0[2 * oo][1]     = ffma2(w2.x, g1, h0[2 * oo][1]);
            h0[2 * oo + 1][0] = ffma2(w2.y, g0, h0[2 * oo + 1][0]);
            h0[2 * oo + 1][1] = ffma2(w2.y, g1, h0[2 * oo + 1][1]);
        }
    }

    ull* dbase = (ull*)dst + (size_t)b * 32 * 131072 + u0;

    for (int cls = 0; cls < 32; cls++) {
        const ull* P = s_params + cls * 154;
        const ulonglong2* P2 = (const ulonglong2*)P;

        ull t1[8][2];
#pragma unroll
        for (int j = 0; j < 8; j++) {
            ull bias = P[136 + j];
            t1[j][0] = bias;
            t1[j][1] = bias;
        }
#pragma unroll
        for (int kk = 0; kk < 4; kk++) {
#pragma unroll
            for (int j = 0; j < 8; j++) {
                ulonglong2 w2 = P2[j * 4 + kk];
                t1[j][0] = ffma2(w2.x, h0[2 * kk][0],     t1[j][0]);
                t1[j][1] = ffma2(w2.x, h0[2 * kk][1],     t1[j][1]);
                t1[j][0] = ffma2(w2.y, h0[2 * kk + 1][0], t1[j][0]);
                t1[j][1] = ffma2(w2.y, h0[2 * kk + 1][1], t1[j][1]);
            }
        }
#pragma unroll
        for (int j = 0; j < 8; j++) {
            t1[j][0] = relu2(t1[j][0]);
            t1[j][1] = relu2(t1[j][1]);
        }

        ull y0 = P[152], y1 = P[152];
#pragma unroll
        for (int j = 0; j < 8; j++) {
            ull bias = P[144 + j];
            ull t20 = bias, t21 = bias;
#pragma unroll
            for (int kk = 0; kk < 4; kk++) {
                ulonglong2 w2 = P2[32 + j * 4 + kk];
                t20 = ffma2(w2.x, t1[2 * kk][0],     t20);
                t21 = ffma2(w2.x, t1[2 * kk][1],     t21);
                t20 = ffma2(w2.y, t1[2 * kk + 1][0], t20);
                t21 = ffma2(w2.y, t1[2 * kk + 1][1], t21);
            }
            ull w3 = P[128 + j];
            y0 = ffma2(w3, relu2(t20), y0);
            y1 = ffma2(w3, relu2(t21), y1);
        }

        ull* dp = dbase + (size_t)cls * 131072;
        dp[0]   = y0;
        dp[256] = y1;
    }
}

// ============================================================================
extern "C" void kernel_launch(void* const* d_in, const int* in_sizes, int n_in,
                              void* d_out, int out_size) {
    const float* x      = (const float*)d_in[0];
    const float* outp   = (const float*)d_in[1];
    const float* te     = (const float*)d_in[2];
    const float* gn1_g  = (const float*)d_in[3];
    const float* gn1_b  = (const float*)d_in[4];
    const float* gap_w  = (const float*)d_in[5];
    const float* gap_b  = (const float*)d_in[6];
    const float* ctrl_w = (const float*)d_in[7];
    const float* ctrl_b = (const float*)d_in[8];
    const float* gn2_g  = (const float*)d_in[9];
    const float* gn2_b  = (const float*)d_in[10];
    const float* pre_w  = (const float*)d_in[11];
    const float* pre_b  = (const float*)d_in[12];
    float* dst = (float*)d_out;

    k_stats<<<800, 256>>>(outp, x, gn1_g, gn1_b);
    k_xfeat<<<16, 256>>>(gap_w, gap_b);
    k_gparams<<<35, 1024>>>(ctrl_w, ctrl_b, te);
    k_main<<<512, 256>>>(outp, gn2_g, gn2_b, pre_w, pre_b, dst);
}

// round 9
// speedup vs baseline: 1.6094x; 1.0112x over previous
#include <cuda_runtime.h>

#define EPS 1e-5f
typedef unsigned long long ull;

// ---------------- packed f32x2 helpers (B300 dual-rate FP32 path) ----------
__device__ __forceinline__ ull pack2(float x, float y) {
    ull r; asm("mov.b64 %0, {%1,%2};" : "=l"(r) : "f"(x), "f"(y)); return r;
}
__device__ __forceinline__ ull dup2(float x) { return pack2(x, x); }
__device__ __forceinline__ void unpack2(ull a, float& x, float& y) {
    asm("mov.b64 {%0,%1}, %2;" : "=f"(x), "=f"(y) : "l"(a));
}
__device__ __forceinline__ ull ffma2(ull a, ull b, ull c) {
    ull d; asm("fma.rn.f32x2 %0, %1, %2, %3;" : "=l"(d) : "l"(a), "l"(b), "l"(c));
    return d;
}
__device__ __forceinline__ ull relu2(ull a) {
    float x, y; unpack2(a, x, y);
    x = fmaxf(x, 0.f); y = fmaxf(y, 0.f);
    return pack2(x, y);
}
__device__ __forceinline__ float warp_sum(float v) {
#pragma unroll
    for (int o = 16; o > 0; o >>= 1)
        v += __shfl_down_sync(0xffffffffu, v, o);
    return v;
}

// ---------------- scratch (device globals: no allocs allowed) --------------
__device__ float g_pooled[2 * 768];
__device__ float g_xfeat[2 * 256];
__device__ float g_G1[2 * 153];     // ctrl_w[:, :256] @ x_feat + ctrl_b
__device__ float g_G2[32 * 153];    // ctrl_w[:, 256:] @ te
__device__ float g_part[2 * 16 * 24 * 2];
__device__ float g_stats[2 * 16 * 2];   // (mean, rstd) per (b, group)
__device__ int   g_work;                // k_main work-queue counter

// ============================================================================
// Kernel 1: k_stats — fused independent stats
//   blocks   0..767: GN2 partial sums over out (2,48,64^3)
//   blocks 768..799: GN1(x)+ReLU+pool -> g_pooled (2,768)
// ============================================================================
__global__ void k_stats(const float* __restrict__ outp,
                        const float* __restrict__ x,
                        const float* __restrict__ g1g,
                        const float* __restrict__ g1b) {
    __shared__ float rs[256], rss[256];
    int t = threadIdx.x;

    if (blockIdx.x < 768) {
        int bg = blockIdx.x / 24, part = blockIdx.x % 24;
        const float4* base = (const float4*)(outp + (size_t)bg * 786432) + (size_t)part * 8192;
        float s = 0.f, ss = 0.f;
        for (int i = t; i < 8192; i += 256) {
            float4 v = base[i];
            s  += v.x + v.y + v.z + v.w;
            ss += v.x * v.x + v.y * v.y + v.z * v.z + v.w * v.w;
        }
        rs[t] = s; rss[t] = ss;
        __syncthreads();
        for (int o = 128; o > 0; o >>= 1) {
            if (t < o) { rs[t] += rs[t + o]; rss[t] += rss[t + o]; }
            __syncthreads();
        }
        if (t == 0) {
            g_part[blockIdx.x * 2]     = rs[0];
            g_part[blockIdx.x * 2 + 1] = rss[0];
        }
    } else {
        int bg = blockIdx.x - 768;            // 0..31
        int b = bg >> 4, g = bg & 15;
        const float* base = x + ((size_t)b * 768 + (size_t)g * 48) * 512;

        float s = 0.f, ss = 0.f;
        const float4* b4 = (const float4*)base;
        for (int i = t; i < 6144; i += 256) {
            float4 v = b4[i];
            s  += v.x + v.y + v.z + v.w;
            ss += v.x * v.x + v.y * v.y + v.z * v.z + v.w * v.w;
        }
        rs[t] = s; rss[t] = ss;
        __syncthreads();
        for (int o = 128; o > 0; o >>= 1) {
            if (t < o) { rs[t] += rs[t + o]; rss[t] += rss[t + o]; }
            __syncthreads();
        }
        __shared__ float s_mean, s_rstd;
        if (t == 0) {
            float mean = rs[0] * (1.f / 24576.f);
            float var  = rss[0] * (1.f / 24576.f) - mean * mean;
            s_mean = mean;
            s_rstd = rsqrtf(var + EPS);
        }
        __syncthreads();
        float mean = s_mean, rstd = s_rstd;

        int warp = t >> 5, lane = t & 31;
        for (int c = warp; c < 48; c += 8) {
            int ch = g * 48 + c;
            float sc = rstd * g1g[ch];
            float sh = g1b[ch] - mean * sc;
            const float* cb = base + (size_t)c * 512;
            float acc = 0.f;
            for (int i = lane; i < 512; i += 32)
                acc += fmaxf(fmaf(cb[i], sc, sh), 0.f);
            acc = warp_sum(acc);
            if (lane == 0) g_pooled[b * 768 + ch] = acc * (1.f / 512.f);
        }
    }
}

// ============================================================================
// Kernel 2: x_feat = pooled @ gap_w.T + gap_b   (2,256)
// ============================================================================
__global__ void k_xfeat(const float* __restrict__ gap_w,
                        const float* __restrict__ gap_b) {
    int b   = blockIdx.x >> 3;
    int sub = blockIdx.x & 7;
    int warp = threadIdx.x >> 5, lane = threadIdx.x & 31;

    __shared__ float sp[768];
    for (int i = threadIdx.x; i < 768; i += 256) sp[i] = g_pooled[b * 768 + i];
    __syncthreads();

    for (int q = 0; q < 4; q++) {
        int f = sub * 32 + q * 8 + warp;
        const float* wr = gap_w + (size_t)f * 768;
        float acc = 0.f;
        for (int i = lane; i < 768; i += 32)
            acc = fmaf(wr[i], sp[i], acc);
        acc = warp_sum(acc);
        if (lane == 0) g_xfeat[b * 256 + f] = acc + gap_b[f];
    }
}

// ============================================================================
// Kernel 3: k_gparams — flat warp-per-row + gn2 finalize + work-counter reset
// ============================================================================
__global__ void k_gparams(const float* __restrict__ ctrl_w,
                          const float* __restrict__ ctrl_b,
                          const float* __restrict__ te) {
    int blk = blockIdx.x;
    int t = threadIdx.x;

    if (blk == 34) {
        if (t == 0) g_work = 0;           // reset k_main work queue every launch
        if (t < 32) {
            int bg = t;
            float s = 0.f, ss = 0.f;
            for (int p = 0; p < 24; p++) {
                s  += g_part[(bg * 24 + p) * 2];
                ss += g_part[(bg * 24 + p) * 2 + 1];
            }
            float mean = s * (1.f / 786432.f);
            float var  = ss * (1.f / 786432.f) - mean * mean;
            g_stats[bg * 2]     = mean;
            g_stats[bg * 2 + 1] = rsqrtf(var + EPS);
        }
        return;
    }

    __shared__ float sv[256];
    const float* wbase;
    float* dst;
    bool addb = (blk < 2);
    if (addb) {
        if (t < 256) sv[t] = g_xfeat[blk * 256 + t];
        wbase = ctrl_w;
        dst = g_G1 + blk * 153;
    } else {
        int c = blk - 2;
        if (t < 256) sv[t] = te[c * 256 + t];
        wbase = ctrl_w + 256;
        dst = g_G2 + c * 153;
    }
    __syncthreads();

    int warp = t >> 5, lane = t & 31;
    int p0 = warp, p1 = warp + 32, p2 = warp + 64, p3 = warp + 96, p4 = warp + 128;
    bool v4 = (p4 < 153);
    const float* w0 = wbase + (size_t)p0 * 512;
    const float* w1 = wbase + (size_t)p1 * 512;
    const float* w2 = wbase + (size_t)p2 * 512;
    const float* w3 = wbase + (size_t)p3 * 512;
    const float* w4 = wbase + (size_t)(v4 ? p4 : 0) * 512;

    float a0 = 0.f, a1 = 0.f, a2 = 0.f, a3 = 0.f, a4 = 0.f;
#pragma unroll
    for (int it = 0; it < 8; it++) {
        int idx = it * 32 + lane;
        float v = sv[idx];
        a0 = fmaf(w0[idx], v, a0);
        a1 = fmaf(w1[idx], v, a1);
        a2 = fmaf(w2[idx], v, a2);
        a3 = fmaf(w3[idx], v, a3);
        a4 = fmaf(w4[idx], v, a4);
    }
    a0 = warp_sum(a0); a1 = warp_sum(a1); a2 = warp_sum(a2);
    a3 = warp_sum(a3); a4 = warp_sum(a4);
    if (lane == 0) {
        if (addb) {
            dst[p0] = a0 + ctrl_b[p0];
            dst[p1] = a1 + ctrl_b[p1];
            dst[p2] = a2 + ctrl_b[p2];
            dst[p3] = a3 + ctrl_b[p3];
            if (v4) dst[p4] = a4 + ctrl_b[p4];
        } else {
            dst[p0] = a0;
            dst[p1] = a1;
            dst[p2] = a2;
            dst[p3] = a3;
            if (v4) dst[p4] = a4;
        }
    }
}

// ============================================================================
// Kernel 4: persistent k_main — 296 CTAs, atomic chunk queue
// Inner math identical to round-4/8 known-good body; prologue cached per b.
// ============================================================================
__global__ void __launch_bounds__(256, 2)
k_main(const float* __restrict__ outp,
       const float* __restrict__ g2g, const float* __restrict__ g2b,
       const float* __restrict__ pre_w, const float* __restrict__ pre_b,
       float* __restrict__ dst) {
    __shared__ ull s_params[32 * 154];         // pad 154 -> 16B align
    __shared__ ull s_prew[48 * 8];             // transposed [c][o]
    __shared__ ull s_preb[8];
    __shared__ ulonglong2 s_gn[48];            // .x=scale .y=shift (dup2'd)
    __shared__ int s_chunk;

    int t = threadIdx.x;

    // b-independent prologue (fenced by first reload's __syncthreads)
    for (int i = t; i < 384; i += 256) {
        int c = i >> 3, o = i & 7;
        s_prew[i] = dup2(pre_w[o * 48 + c]);
    }
    if (t < 8) s_preb[t] = dup2(pre_b[t]);

    int cached_b = -1;                  // uniform across block

    while (true) {
        __syncthreads();                       // prior chunk's smem reads done
        if (t == 0) s_chunk = atomicAdd(&g_work, 1);
        __syncthreads();
        int chunk = s_chunk;
        if (chunk >= 512) break;
        int b = chunk >> 8;

        if (b != cached_b) {
            for (int i = t; i < 32 * 154; i += 256) {
                int cls = i / 154, p = i - cls * 154;
                if (p < 153)
                    s_params[i] = dup2(g_G1[b * 153 + p] + g_G2[cls * 153 + p]);
            }
            if (t >= 32 && t < 80) {
                int c = t - 32;
                int g = c / 3;
                float mean = g_stats[(b * 16 + g) * 2];
                float rstd = g_stats[(b * 16 + g) * 2 + 1];
                float sc = rstd * g2g[c];
                s_gn[c].x = dup2(sc);
                s_gn[c].y = dup2(g2b[c] - mean * sc);
            }
            cached_b = b;
            __syncthreads();
        }

        int u0 = (chunk & 255) * 512 + t;
        const ull* src = (const ull*)outp + (size_t)b * 48 * 131072 + u0;

        ull h0[8][2];
#pragma unroll
        for (int o = 0; o < 8; o++) {
            h0[o][0] = s_preb[o];
            h0[o][1] = s_preb[o];
        }

        ull n0 = src[0], n1 = src[256];
        for (int c = 0; c < 48; c++) {
            ull v0 = n0, v1 = n1;
            if (c < 47) {
                const ull* nx = src + (size_t)(c + 1) * 131072;
                n0 = nx[0]; n1 = nx[256];
            }
            ulonglong2 gn = s_gn[c];
            ull g0 = relu2(ffma2(v0, gn.x, gn.y));
            ull g1 = relu2(ffma2(v1, gn.x, gn.y));
            const ulonglong2* W = (const ulonglong2*)(s_prew + c * 8);
#pragma unroll
            for (int oo = 0; oo < 4; oo++) {
                ulonglong2 w2 = W[oo];
                h0[2 * oo][0]     = ffma2(w2.x, g0, h0[2 * oo][0]);
                h0[2 * oo][1]     = ffma2(w2.x, g1, h0[2 * oo][1]);
                h0[2 * oo + 1][0] = ffma2(w2.y, g0, h0[2 * oo + 1][0]);
                h0[2 * oo + 1][1] = ffma2(w2.y, g1, h0[2 * oo + 1][1]);
            }
        }

        ull* dbase = (ull*)dst + (size_t)b * 32 * 131072 + u0;

        for (int cls = 0; cls < 32; cls++) {
            const ull* P = s_params + cls * 154;
            const ulonglong2* P2 = (const ulonglong2*)P;

            // ---- layer 1: t1 = relu(W1 h0 + b1), biases via LDS.128 ----
            ull t1[8][2];
#pragma unroll
            for (int jj = 0; jj < 4; jj++) {
                ulonglong2 bb = P2[68 + jj];           // b1[2jj], b1[2jj+1]
                t1[2 * jj][0]     = bb.x;
                t1[2 * jj][1]     = bb.x;
                t1[2 * jj + 1][0] = bb.y;
                t1[2 * jj + 1][1] = bb.y;
            }
#pragma unroll
            for (int kk = 0; kk < 4; kk++) {
#pragma unroll
                for (int j = 0; j < 8; j++) {
                    ulonglong2 w2 = P2[j * 4 + kk];
                    t1[j][0] = ffma2(w2.x, h0[2 * kk][0],     t1[j][0]);
                    t1[j][1] = ffma2(w2.x, h0[2 * kk][1],     t1[j][1]);
                    t1[j][0] = ffma2(w2.y, h0[2 * kk + 1][0], t1[j][0]);
                    t1[j][1] = ffma2(w2.y, h0[2 * kk + 1][1], t1[j][1]);
                }
            }
#pragma unroll
            for (int j = 0; j < 8; j++) {
                t1[j][0] = relu2(t1[j][0]);
                t1[j][1] = relu2(t1[j][1]);
            }

            // ---- layers 2+3 folded ----
            ull y0 = P[152], y1 = P[152];
#pragma unroll
            for (int jj = 0; jj < 4; jj++) {
                ulonglong2 bb = P2[72 + jj];           // b2[2jj], b2[2jj+1]
#pragma unroll
                for (int h = 0; h < 2; h++) {
                    int j = 2 * jj + h;
                    ull bias = h ? bb.y : bb.x;
                    ull t20 = bias, t21 = bias;
#pragma unroll
                    for (int kk = 0; kk < 4; kk++) {
                        ulonglong2 w2 = P2[32 + j * 4 + kk];
                        t20 = ffma2(w2.x, t1[2 * kk][0],     t20);
                        t21 = ffma2(w2.x, t1[2 * kk][1],     t21);
                        t20 = ffma2(w2.y, t1[2 * kk + 1][0], t20);
                        t21 = ffma2(w2.y, t1[2 * kk + 1][1], t21);
                    }
                    ull w3 = P[128 + j];
                    y0 = ffma2(w3, relu2(t20), y0);
                    y1 = ffma2(w3, relu2(t21), y1);
                }
            }

            ull* dp = dbase + (size_t)cls * 131072;
            dp[0]   = y0;
            dp[256] = y1;
        }
    }
}

// ============================================================================
extern "C" void kernel_launch(void* const* d_in, const int* in_sizes, int n_in,
                              void* d_out, int out_size) {
    const float* x      = (const float*)d_in[0];
    const float* outp   = (const float*)d_in[1];
    const float* te     = (const float*)d_in[2];
    const float* gn1_g  = (const float*)d_in[3];
    const float* gn1_b  = (const float*)d_in[4];
    const float* gap_w  = (const float*)d_in[5];
    const float* gap_b  = (const float*)d_in[6];
    const float* ctrl_w = (const float*)d_in[7];
    const float* ctrl_b = (const float*)d_in[8];
    const float* gn2_g  = (const float*)d_in[9];
    const float* gn2_b  = (const float*)d_in[10];
    const float* pre_w  = (const float*)d_in[11];
    const float* pre_b  = (const float*)d_in[12];
    float* dst = (float*)d_out;

    k_stats<<<800, 256>>>(outp, x, gn1_g, gn1_b);
    k_xfeat<<<16, 256>>>(gap_w, gap_b);
    k_gparams<<<35, 1024>>>(ctrl_w, ctrl_b, te);
    k_main<<<296, 256>>>(outp, gn2_g, gn2_b, pre_w, pre_b, dst);
}